// round 17
// baseline (speedup 1.0000x reference)
#include <cuda_runtime.h>
#include <cuda_bf16.h>
#include <cuda_fp16.h>
#include <math.h>
#include <stdint.h>

// Problem constants
#define BATCH 2
#define SEQ 2048
#define TOK (BATCH*SEQ)          // 4096
#define HID 3584
#define NH 32
#define NKV 4
#define HD 128
#define QD (NH*HD)               // 4096
#define KVD (NKV*HD)             // 512

// fp32 scratch
__device__ float g_q[(size_t)TOK*QD];
// fp16 scratch
__device__ __half g_h1[(size_t)TOK*HID];
__device__ __half g_wq[(size_t)QD*HID];
__device__ __half g_wk[(size_t)KVD*HID];
__device__ __half g_wv[(size_t)KVD*HID];
__device__ __half g_wo[(size_t)HID*QD];
__device__ __half g_a1[(size_t)TOK*QD];
__device__ __half g_k1[(size_t)TOK*KVD];
__device__ __half g_v1[(size_t)TOK*KVD];

// ===========================================================================
// PTX helpers
// ===========================================================================
__device__ __forceinline__ uint32_t smem_u32(const void* p) {
    uint32_t a;
    asm("{ .reg .u64 t; cvta.to.shared.u64 t, %1; cvt.u32.u64 %0, t; }" : "=r"(a) : "l"(p));
    return a;
}
__device__ __forceinline__ void cp_async16(uint32_t dst, const void* src) {
    asm volatile("cp.async.cg.shared.global [%0], [%1], 16;" :: "r"(dst), "l"(src) : "memory");
}
#define CP_COMMIT() asm volatile("cp.async.commit_group;" ::: "memory")
#define CP_WAIT(n)  asm volatile("cp.async.wait_group %0;" :: "n"(n) : "memory")

__device__ __forceinline__ void ldm4(uint32_t* r, uint32_t addr) {
    asm volatile("ldmatrix.sync.aligned.m8n8.x4.shared.b16 {%0,%1,%2,%3}, [%4];"
                 : "=r"(r[0]), "=r"(r[1]), "=r"(r[2]), "=r"(r[3]) : "r"(addr));
}
__device__ __forceinline__ void ldm4t(uint32_t* r, uint32_t addr) {
    asm volatile("ldmatrix.sync.aligned.m8n8.x4.trans.shared.b16 {%0,%1,%2,%3}, [%4];"
                 : "=r"(r[0]), "=r"(r[1]), "=r"(r[2]), "=r"(r[3]) : "r"(addr));
}
__device__ __forceinline__ void mma_f16(float* c, const uint32_t* a, const uint32_t* b) {
    asm volatile("mma.sync.aligned.m16n8k16.row.col.f32.f16.f16.f32 "
                 "{%0,%1,%2,%3}, {%4,%5,%6,%7}, {%8,%9}, {%0,%1,%2,%3};"
                 : "+f"(c[0]), "+f"(c[1]), "+f"(c[2]), "+f"(c[3])
                 : "r"(a[0]), "r"(a[1]), "r"(a[2]), "r"(a[3]), "r"(b[0]), "r"(b[1]));
}
__device__ __forceinline__ uint32_t cvt2h(float hi, float lo) {
    uint32_t r;
    asm("cvt.rn.f16x2.f32 %0, %1, %2;" : "=r"(r) : "f"(hi), "f"(lo));
    return r;
}
__device__ __forceinline__ float hloF(uint32_t p) {
    return __half2float(__ushort_as_half((unsigned short)(p & 0xffffu)));
}
__device__ __forceinline__ float hhiF(uint32_t p) {
    return __half2float(__ushort_as_half((unsigned short)(p >> 16)));
}

// fast 2^t on the FMA pipe (no MUFU); exp2(0) == 1.0 exactly
__device__ __forceinline__ float fast_exp2(float t) {
    t = fmaxf(t, -120.0f);
    float r = t + 12582912.0f;
    float n = r - 12582912.0f;
    float f = t - n;
    int   ni = __float_as_int(r);
    float p = 1.3392112e-3f;
    p = fmaf(p, f, 9.6183463e-3f);
    p = fmaf(p, f, 5.5503277e-2f);
    p = fmaf(p, f, 2.4022652e-1f);
    p = fmaf(p, f, 6.9314718e-1f);
    p = fmaf(p, f, 1.0f);
    return __int_as_float(__float_as_int(p) + (ni << 23));
}

// ===========================================================================
// Fused split (vectorized float4 -> 2x half2): all five fp32 -> fp16.
// All region sizes are multiples of 4.
// ===========================================================================
#define SPL_N0 (TOK*HID)
#define SPL_N1 (SPL_N0 + QD*HID)
#define SPL_N2 (SPL_N1 + KVD*HID)
#define SPL_N3 (SPL_N2 + KVD*HID)
#define SPL_N4 (SPL_N3 + HID*QD)
#define SPL_V4 (SPL_N4/4)

__global__ void split_all_kernel(
    const float* __restrict__ x0, const float* __restrict__ x1,
    const float* __restrict__ x2, const float* __restrict__ x3,
    const float* __restrict__ x4,
    __half* __restrict__ h1,
    __half* __restrict__ wq, __half* __restrict__ wk,
    __half* __restrict__ wv, __half* __restrict__ wo)
{
    int v = blockIdx.x * 256 + threadIdx.x;
    if (v >= SPL_V4) return;
    int i = v * 4;
    const float* x; __half* dst; int off;
    if (i < SPL_N0)      { x = x0; dst = h1; off = i; }
    else if (i < SPL_N1) { x = x1; dst = wq; off = i - SPL_N0; }
    else if (i < SPL_N2) { x = x2; dst = wk; off = i - SPL_N1; }
    else if (i < SPL_N3) { x = x3; dst = wv; off = i - SPL_N2; }
    else                 { x = x4; dst = wo; off = i - SPL_N3; }
    float4 val = *(const float4*)(x + off);
    uint2 hp;
    hp.x = cvt2h(val.y, val.x);
    hp.y = cvt2h(val.w, val.z);
    *(uint2*)(dst + off) = hp;
}

// ===========================================================================
// mma.sync fp16 GEMM (single-term): C = A * B^T.
// 128x128 tiles, K64 stages (two K32 sub-tiles per stage), 3-stage cp.async,
// single barrier per stage, 8 warps (2x4), warp 64x32. 1 CTA/SM.
// ===========================================================================
#define TSTR 40
#define TILE_B (128*TSTR*2)           // 10240 bytes per 128x32 tile
#define STAGE_B (4*TILE_B)            // 40960: A0,B0,A1,B1
#define GEMM_SMEM (3*STAGE_B)         // 122880

// issues one K32 sub-tile pair (A,B) at sub-tile base
__device__ __forceinline__ void gemm_issue_sub(
    uint32_t sub, const __half* pA, const __half* pB, int K, int ko, int tid)
{
    #pragma unroll
    for (int i = 0; i < 2; i++) {
        int c = tid + (i << 8);
        int row = c >> 2;
        int kc  = c & 3;
        uint32_t dst = (uint32_t)(row * TSTR + kc * 8) * 2;
        size_t src = (size_t)row * K + ko + kc * 8;
        cp_async16(sub + dst, pA + src);
        cp_async16(sub + TILE_B + dst, pB + src);
    }
}
__device__ __forceinline__ void gemm_issue_stage(
    uint32_t sstage, const __half* pA, const __half* pB, int K, int ko, int tid)
{
    gemm_issue_sub(sstage,            pA, pB, K, ko,      tid);
    gemm_issue_sub(sstage + 2*TILE_B, pA, pB, K, ko + 32, tid);
}

__device__ __forceinline__ void gemm_mainloop(
    const __half* __restrict__ pA, const __half* __restrict__ pB,
    int K, char* smem, float acc[4][4][4])
{
    uint32_t sbase = smem_u32(smem);
    const int tid  = threadIdx.x;
    const int lane = tid & 31;
    const int wid  = tid >> 5;
    const int wm   = wid >> 2;
    const int wn   = wid & 3;

    const uint32_t laneA = (uint32_t)((lane & 15) * TSTR + ((lane >> 4) << 3)) * 2;
    const uint32_t laneB = (uint32_t)(((lane & 7) + ((lane >> 4) << 3)) * TSTR
                                      + (((lane >> 3) & 1) << 3)) * 2;

    #pragma unroll
    for (int i = 0; i < 4; i++)
        #pragma unroll
        for (int j = 0; j < 4; j++)
            #pragma unroll
            for (int r = 0; r < 4; r++) acc[i][j][r] = 0.f;

    const int KT = K >> 6;            // K64 stages (56 or 64)
    gemm_issue_stage(sbase, pA, pB, K, 0, tid);
    CP_COMMIT();
    gemm_issue_stage(sbase + STAGE_B, pA, pB, K, 64, tid);
    CP_COMMIT();

    int cur = 0, pf = 2;
    for (int kt = 0; kt < KT; kt++) {
        if (kt + 1 < KT) { CP_WAIT(1); } else { CP_WAIT(0); }
        __syncthreads();

        uint32_t st = sbase + (uint32_t)cur * STAGE_B;
        #pragma unroll
        for (int sub = 0; sub < 2; sub++) {
            uint32_t sA = st + (uint32_t)sub * (2*TILE_B);
            uint32_t sB = sA + TILE_B;
            #pragma unroll
            for (int kk = 0; kk < 2; kk++) {
                uint32_t a[4][4];
                #pragma unroll
                for (int mi = 0; mi < 4; mi++) {
                    uint32_t aoff = (uint32_t)(((wm * 64 + mi * 16) * TSTR + kk * 16) * 2);
                    ldm4(a[mi], sA + aoff + laneA);
                }
                uint32_t b[4][2];
                #pragma unroll
                for (int nj2 = 0; nj2 < 2; nj2++) {
                    uint32_t boff = (uint32_t)(((wn * 32 + nj2 * 16) * TSTR + kk * 16) * 2);
                    uint32_t r[4];
                    ldm4(r, sB + boff + laneB);
                    b[nj2*2][0] = r[0]; b[nj2*2][1] = r[1];
                    b[nj2*2+1][0] = r[2]; b[nj2*2+1][1] = r[3];
                }
                #pragma unroll
                for (int mi = 0; mi < 4; mi++)
                    #pragma unroll
                    for (int nj = 0; nj < 4; nj++)
                        mma_f16(acc[mi][nj], a[mi], b[nj]);
            }
        }

        // refill stage (kt+2)%3 == (kt-1)%3: drained after top-of-kt barrier
        if (kt + 2 < KT) {
            gemm_issue_stage(sbase + (uint32_t)pf * STAGE_B, pA, pB, K,
                             (kt + 2) << 6, tid);
            CP_COMMIT();
        }
        cur++; if (cur == 3) cur = 0;
        pf++;  if (pf == 3)  pf = 0;
    }
}

// fp32 epilogue (Q and O projections)
__device__ __forceinline__ void epilogue_f32(float acc[4][4][4], float* Ct, int N)
{
    const int lane = threadIdx.x & 31;
    const int wid  = threadIdx.x >> 5;
    const int wm = wid >> 2, wn = wid & 3;
    const int g = lane >> 2, tg = lane & 3;
    #pragma unroll
    for (int mi = 0; mi < 4; mi++) {
        int row = wm * 64 + mi * 16 + g;
        #pragma unroll
        for (int nj = 0; nj < 4; nj++) {
            int col = wn * 32 + nj * 8 + tg * 2;
            float* p0 = Ct + (size_t)row * N + col;
            float* p1 = p0 + (size_t)8 * N;
            p0[0] = acc[mi][nj][0]; p0[1] = acc[mi][nj][1];
            p1[0] = acc[mi][nj][2]; p1[1] = acc[mi][nj][3];
        }
    }
}

// Fused Q/K/V projection: grid (40, TOK/128). bx 0-31: Q (fp32 out);
// bx 32-35: K (rope + single fp16); bx 36-39: V (single fp16).
__global__ void __launch_bounds__(256, 1)
gemm_qkv(const __half* __restrict__ h1,
         const __half* __restrict__ wq, const __half* __restrict__ wk,
         const __half* __restrict__ wv,
         float* __restrict__ qb,
         __half* __restrict__ k1, __half* __restrict__ v1,
         const int* __restrict__ pos32)
{
    extern __shared__ char smem[];
    const int bx = blockIdx.x;
    const int bm = blockIdx.y << 7;
    const int tid = threadIdx.x;
    const __half* bp;
    int bn;
    if (bx < 32)      { bp = wq; bn = bx << 7; }
    else if (bx < 36) { bp = wk; bn = (bx - 32) << 7; }
    else              { bp = wv; bn = (bx - 36) << 7; }

    float acc[4][4][4];
    gemm_mainloop(h1 + (size_t)bm * HID, bp + (size_t)bn * HID, HID, smem, acc);

    const int lane = tid & 31;
    const int wid  = tid >> 5;
    const int wm = wid >> 2, wn = wid & 3;
    const int g = lane >> 2, tg = lane & 3;

    if (bx < 32) {
        epilogue_f32(acc, qb + (size_t)bm * QD + bn, QD);
    } else if (bx < 36) {
        // K: stage acc to smem, then rope + single fp16 round
        float* sacc = (float*)smem;     // [128][132] = 67584 <= 122880
        __syncthreads();
        #pragma unroll
        for (int mi = 0; mi < 4; mi++) {
            int row = wm * 64 + mi * 16 + g;
            #pragma unroll
            for (int nj = 0; nj < 4; nj++) {
                int col = wn * 32 + nj * 8 + tg * 2;
                sacc[row * 132 + col]     = acc[mi][nj][0];
                sacc[row * 132 + col + 1] = acc[mi][nj][1];
                sacc[(row + 8) * 132 + col]     = acc[mi][nj][2];
                sacc[(row + 8) * 132 + col + 1] = acc[mi][nj][3];
            }
        }
        __syncthreads();
        const bool is64 = (pos32[1] == 0);
        #pragma unroll
        for (int i = 0; i < 32; i++) {
            int idx = tid + (i << 8);
            int row = idx >> 6;
            int d   = idx & 63;
            int t   = bm + row;
            int p = is64 ? pos32[2 * t] : pos32[t];
            float invf = powf(1.0e6f, -(float)d * (1.0f / 64.0f));
            float sv, cv;
            sincosf((float)p * invf, &sv, &cv);
            float x1 = sacc[row * 132 + d];
            float x2 = sacc[row * 132 + d + 64];
            size_t off = (size_t)t * KVD + bn + d;
            k1[off]      = __float2half(x1 * cv - x2 * sv);
            k1[off + 64] = __float2half(x2 * cv + x1 * sv);
        }
    } else {
        // V: single fp16 round
        #pragma unroll
        for (int mi = 0; mi < 4; mi++) {
            int row = wm * 64 + mi * 16 + g;
            #pragma unroll
            for (int nj = 0; nj < 4; nj++) {
                int col = wn * 32 + nj * 8 + tg * 2;
                size_t off0 = (size_t)(bm + row) * KVD + bn + col;
                size_t off1 = off0 + (size_t)8 * KVD;
                *(uint32_t*)(v1 + off0) = cvt2h(acc[mi][nj][1], acc[mi][nj][0]);
                *(uint32_t*)(v1 + off1) = cvt2h(acc[mi][nj][3], acc[mi][nj][2]);
            }
        }
    }
}

// O-projection: single-term fp16
__global__ void __launch_bounds__(256, 1)
gemm_nt_single(const __half* __restrict__ A, const __half* __restrict__ B,
               float* __restrict__ C, int N, int K)
{
    extern __shared__ char smem[];
    const int bm = blockIdx.y << 7;
    const int bn = blockIdx.x << 7;
    float acc[4][4][4];
    gemm_mainloop(A + (size_t)bm * K, B + (size_t)bn * K, K, smem, acc);
    epilogue_f32(acc, C + (size_t)bm * N + bn, N);
}

// ===========================================================================
// Flash attention: fp16 mma, FMA-pipe exp2, non-causal.
// QK: Q hi/lo x K single (2 terms). PV: P single x V single (1 term).
// KV stages hold 128 rows (two 64-row halves); one wait per stage.
// Q-RoPE fused into Q-load. Epilogue writes single fp16 (feeds O-proj).
// ===========================================================================
#define FSTR 136
#define FA_Q_B (128*FSTR*2)               // 34816
#define FA_T_B (64*FSTR*2)                // 17408
#define FA_ST_B (4*FA_T_B)                // 69632: K0,V0,K1,V1
#define FA_SMEM (2*FA_Q_B + 2*FA_ST_B)    // 208896

__device__ __forceinline__ void fa_load_kv(
    uint32_t stage, const __half* __restrict__ K1, const __half* __restrict__ V1,
    size_t rowbase, int kvoff, int tid)
{
    #pragma unroll
    for (int comp = 0; comp < 2; comp++) {
        const __half* g = (comp == 0) ? K1 : V1;
        #pragma unroll
        for (int jj = 0; jj < 8; jj++) {          // 128 rows
            int cc = tid + (jj << 8);             // 0..2047
            int row = cc >> 4, kc = cc & 15;
            int half = row >> 6, r64 = row & 63;
            uint32_t dst = stage + (uint32_t)half * (2*FA_T_B)
                         + (uint32_t)comp * FA_T_B
                         + (uint32_t)(r64 * 272 + kc * 16);
            cp_async16(dst, g + (rowbase + row) * KVD + kvoff + kc * 8);
        }
    }
}

__global__ void __launch_bounds__(256, 1)
flash_attn_mma(const float* __restrict__ Q, const int* __restrict__ pos32,
               const __half* __restrict__ K1, const __half* __restrict__ V1,
               __half* __restrict__ a1)
{
    extern __shared__ char smem[];
    uint32_t sb = smem_u32(smem);
    const uint32_t sQH = sb;
    const uint32_t sQL = sb + FA_Q_B;
    const uint32_t sST = sb + 2 * FA_Q_B;

    const int tid = threadIdx.x, lane = tid & 31, w = tid >> 5;
    const int bh = blockIdx.y, b = bh >> 5, h = bh & 31, kvh = h >> 3;
    const int q0 = blockIdx.x << 7;
    const int g = lane >> 2, t = lane & 3;

    // --- Q load + RoPE + scale(1/sqrt(d)*log2e) + fp16 hi/lo split ---
    const float qsc = 0.08838834764831843f * 1.4426950408889634f;
    const float* Qg = Q + (size_t)(b * SEQ + q0) * QD + h * HD;
    const bool is64 = (pos32[1] == 0);
    #pragma unroll
    for (int i = 0; i < 8; i++) {
        int idx = tid + (i << 8);
        int row = idx >> 4;
        int d4  = (idx & 15) << 2;
        int tok = b * SEQ + q0 + row;
        int p = is64 ? pos32[2 * tok] : pos32[tok];
        float4 xa = *(const float4*)(Qg + (size_t)row * QD + d4);
        float4 xb = *(const float4*)(Qg + (size_t)row * QD + d4 + 64);
        float ya[4], yb[4];
        const float* x1 = &xa.x;
        const float* x2 = &xb.x;
        #pragma unroll
        for (int j = 0; j < 4; j++) {
            int d = d4 + j;
            float invf = powf(1.0e6f, -(float)d * (1.0f / 64.0f));
            float sv, cv;
            sincosf((float)p * invf, &sv, &cv);
            ya[j] = (x1[j] * cv - x2[j] * sv) * qsc;
            yb[j] = (x2[j] * cv + x1[j] * sv) * qsc;
        }
        uint32_t ha01 = cvt2h(ya[1], ya[0]);
        uint32_t ha23 = cvt2h(ya[3], ya[2]);
        uint32_t la01 = cvt2h(ya[1] - hhiF(ha01), ya[0] - hloF(ha01));
        uint32_t la23 = cvt2h(ya[3] - hhiF(ha23), ya[2] - hloF(ha23));
        uint32_t hb01 = cvt2h(yb[1], yb[0]);
        uint32_t hb23 = cvt2h(yb[3], yb[2]);
        uint32_t lb01 = cvt2h(yb[1] - hhiF(hb01), yb[0] - hloF(hb01));
        uint32_t lb23 = cvt2h(yb[3] - hhiF(hb23), yb[2] - hloF(hb23));
        uint32_t off1 = (uint32_t)(row * 272 + d4 * 2);
        uint32_t off2 = (uint32_t)(row * 272 + (d4 + 64) * 2);
        *(uint2*)(smem + (sQH - sb) + off1) = make_uint2(ha01, ha23);
        *(uint2*)(smem + (sQL - sb) + off1) = make_uint2(la01, la23);
        *(uint2*)(smem + (sQH - sb) + off2) = make_uint2(hb01, hb23);
        *(uint2*)(smem + (sQL - sb) + off2) = make_uint2(lb01, lb23);
    }

    float m0 = -1e30f, m1 = -1e30f, l0 = 0.f, l1 = 0.f;
    float o[16][4];
    #pragma unroll
    for (int nd = 0; nd < 16; nd++)
        #pragma unroll
        for (int c = 0; c < 4; c++) o[nd][c] = 0.f;

    const size_t kvbase = (size_t)b * SEQ;
    const int kvoff = kvh * HD;

    const uint32_t lA = (uint32_t)(((lane & 15) * FSTR + ((lane >> 4) << 3)) * 2);
    const uint32_t lB = (uint32_t)((((lane & 7) + ((lane >> 4) << 3)) * FSTR
                                    + (((lane >> 3) & 1) << 3)) * 2);
    const uint32_t lV = (uint32_t)((((lane & 7) + (((lane >> 3) & 1) << 3)) * FSTR
                                    + (((lane >> 4) & 1) << 3)) * 2);

    fa_load_kv(sST, K1, V1, kvbase, kvoff, tid);
    CP_COMMIT();

    const int NT = SEQ / 128;   // 16 stages
    for (int kt = 0; kt < NT; kt++) {
        if (kt + 1 < NT) {
            fa_load_kv(sST + ((kt + 1) & 1) * FA_ST_B, K1, V1,
                       kvbase + (size_t)(kt + 1) * 128, kvoff, tid);
            CP_COMMIT();
            CP_WAIT(1);
        } else {
            CP_WAIT(0);
        }
        __syncthreads();

        const uint32_t stage = sST + (kt & 1) * FA_ST_B;
        #pragma unroll
        for (int hf2 = 0; hf2 < 2; hf2++) {
            const uint32_t st = stage + (uint32_t)hf2 * (2*FA_T_B);
            const uint32_t sK = st, sV = st + FA_T_B;

            float s[8][4];
            #pragma unroll
            for (int j = 0; j < 8; j++)
                #pragma unroll
                for (int c = 0; c < 4; c++) s[j][c] = 0.f;

            #pragma unroll
            for (int kk = 0; kk < 8; kk++) {
                uint32_t qh[4], ql[4];
                uint32_t qoff = (uint32_t)((w * 16 * FSTR + kk * 16) * 2);
                ldm4(qh, sQH + qoff + lA);
                ldm4(ql, sQL + qoff + lA);
                #pragma unroll
                for (int nj2 = 0; nj2 < 4; nj2++) {
                    uint32_t koff = (uint32_t)((nj2 * 16 * FSTR + kk * 16) * 2);
                    uint32_t rk[4];
                    ldm4(rk, sK + koff + lB);
                    mma_f16(s[nj2*2],   qh, rk);     mma_f16(s[nj2*2+1], qh, rk + 2);
                    mma_f16(s[nj2*2],   ql, rk);     mma_f16(s[nj2*2+1], ql, rk + 2);
                }
            }

            float mx0 = -1e30f, mx1 = -1e30f;
            #pragma unroll
            for (int j = 0; j < 8; j++) {
                mx0 = fmaxf(mx0, fmaxf(s[j][0], s[j][1]));
                mx1 = fmaxf(mx1, fmaxf(s[j][2], s[j][3]));
            }
            mx0 = fmaxf(mx0, __shfl_xor_sync(0xffffffffu, mx0, 1));
            mx0 = fmaxf(mx0, __shfl_xor_sync(0xffffffffu, mx0, 2));
            mx1 = fmaxf(mx1, __shfl_xor_sync(0xffffffffu, mx1, 1));
            mx1 = fmaxf(mx1, __shfl_xor_sync(0xffffffffu, mx1, 2));
            float mn0 = fmaxf(m0, mx0), mn1 = fmaxf(m1, mx1);

            bool newmax = (mn0 > m0) || (mn1 > m1);
            if (__any_sync(0xffffffffu, newmax)) {
                float al0 = fast_exp2(m0 - mn0), al1 = fast_exp2(m1 - mn1);
                l0 *= al0; l1 *= al1;
                #pragma unroll
                for (int nd = 0; nd < 16; nd++) {
                    o[nd][0] *= al0; o[nd][1] *= al0;
                    o[nd][2] *= al1; o[nd][3] *= al1;
                }
            }
            m0 = mn0; m1 = mn1;

            uint32_t pf[4][4];
            float sum0 = 0.f, sum1 = 0.f;
            #pragma unroll
            for (int j = 0; j < 8; j++) {
                float p00 = fast_exp2(s[j][0] - mn0);
                float p01 = fast_exp2(s[j][1] - mn0);
                float p10 = fast_exp2(s[j][2] - mn1);
                float p11 = fast_exp2(s[j][3] - mn1);
                sum0 += p00 + p01; sum1 += p10 + p11;
                int kk2 = j >> 1, hf = (j & 1) << 1;
                pf[kk2][hf]     = cvt2h(p01, p00);
                pf[kk2][hf + 1] = cvt2h(p11, p10);
            }
            sum0 += __shfl_xor_sync(0xffffffffu, sum0, 1);
            sum0 += __shfl_xor_sync(0xffffffffu, sum0, 2);
            sum1 += __shfl_xor_sync(0xffffffffu, sum1, 1);
            sum1 += __shfl_xor_sync(0xffffffffu, sum1, 2);
            l0 += sum0;
            l1 += sum1;

            #pragma unroll
            for (int kk2 = 0; kk2 < 4; kk2++) {
                #pragma unroll
                for (int ndp = 0; ndp < 8; ndp++) {
                    uint32_t voff = (uint32_t)((kk2 * 16 * FSTR + ndp * 16) * 2);
                    uint32_t v[4];
                    ldm4t(v, sV + voff + lV);
                    mma_f16(o[ndp*2], pf[kk2], v);   mma_f16(o[ndp*2+1], pf[kk2], v + 2);
                }
            }
        }
        __syncthreads();
    }

    float il0 = 1.f / l0, il1 = 1.f / l1;
    size_t rbase = (size_t)(b * SEQ + q0 + w * 16 + g) * QD + h * HD;
    __half* A1 = a1 + rbase;
    #pragma unroll
    for (int nd = 0; nd < 16; nd++) {
        int col = nd * 8 + t * 2;
        *(uint32_t*)(A1 + col) = cvt2h(o[nd][1] * il0, o[nd][0] * il0);
        *(uint32_t*)(A1 + (size_t)8 * QD + col) = cvt2h(o[nd][3] * il1, o[nd][2] * il1);
    }
}

// ---------------------------------------------------------------------------
extern "C" void kernel_launch(void* const* d_in, const int* in_sizes, int n_in,
                              void* d_out, int out_size)
{
    const float* hidden = (const float*)d_in[0];
    const int*   pos    = (const int*)d_in[1];
    const float* Wq     = (const float*)d_in[2];
    const float* Wk     = (const float*)d_in[3];
    const float* Wv     = (const float*)d_in[4];
    const float* Wo     = (const float*)d_in[5];
    float*       out    = (float*)d_out;

    float *qb;
    cudaGetSymbolAddress((void**)&qb, g_q);
    __half *h1,*wq,*wk,*wv,*wo,*a1,*k1,*v1;
    cudaGetSymbolAddress((void**)&h1, g_h1);
    cudaGetSymbolAddress((void**)&wq, g_wq); cudaGetSymbolAddress((void**)&wk, g_wk);
    cudaGetSymbolAddress((void**)&wv, g_wv); cudaGetSymbolAddress((void**)&wo, g_wo);
    cudaGetSymbolAddress((void**)&a1, g_a1);
    cudaGetSymbolAddress((void**)&k1, g_k1);
    cudaGetSymbolAddress((void**)&v1, g_v1);

    cudaFuncSetAttribute(gemm_qkv, cudaFuncAttributeMaxDynamicSharedMemorySize, GEMM_SMEM);
    cudaFuncSetAttribute(gemm_nt_single, cudaFuncAttributeMaxDynamicSharedMemorySize, GEMM_SMEM);
    cudaFuncSetAttribute(flash_attn_mma, cudaFuncAttributeMaxDynamicSharedMemorySize, FA_SMEM);

    // Splits (vectorized)
    split_all_kernel<<<(SPL_V4 + 255)/256, 256>>>(hidden, Wq, Wk, Wv, Wo,
                                                  h1, wq, wk, wv, wo);

    // Fused Q/K/V projections (K64 stages)
    gemm_qkv<<<dim3(40, TOK/128), 256, GEMM_SMEM>>>(h1, wq, wk, wv,
                                                    qb, k1, v1, pos);

    // Flash attention (Q rope fused; 128-row KV stages)
    flash_attn_mma<<<dim3(SEQ/128, BATCH*NH), 256, FA_SMEM>>>(qb, pos, k1, v1, a1);

    // O projection (K64 stages)
    gemm_nt_single<<<dim3(HID/128, TOK/128), 256, GEMM_SMEM>>>(a1, wo, out, HID, QD);
}